// round 2
// baseline (speedup 1.0000x reference)
#include <cuda_runtime.h>
#include <cuda_bf16.h>

// 3x3 high-pass stencil: y = |(1/8)*sum(8 neighbors) - center| + 1e-5
// x: (8,32,512,512) fp32 treated as 256 independent 512x512 planes, zero-padded.

#define W 512
#define H 512
#define TILE_W 128        // output tile width  (per CTA)
#define TILE_H 8          // output tile height (per CTA)
#define SW 136            // smem row stride in floats (136*4B = 544B, 16B-aligned rows)

__global__ __launch_bounds__(256, 4)
void highpass_kernel(const float* __restrict__ x, float* __restrict__ y) {
    __shared__ float sm[TILE_H + 2][SW];

    const int plane = blockIdx.z;
    const float* __restrict__ xp = x + (size_t)plane * (W * H);
    float* __restrict__ yp       = y + (size_t)plane * (W * H);

    const int c0 = blockIdx.x * TILE_W;   // leftmost output col of tile
    const int r0 = blockIdx.y * TILE_H;   // top output row of tile
    const int tid = threadIdx.y * 32 + threadIdx.x;

    // ---- cooperative fill: interior (10 rows x 32 float4 = 320 vec loads) ----
    // smem col j holds global col (c0 - 1 + (j - 3)) i.e. data cols start at j=4,
    // left halo (c0-1) at j=3, right halo (c0+TILE_W) at j=4+TILE_W.
    #pragma unroll
    for (int v = tid; v < (TILE_H + 2) * 32; v += 256) {
        const int row = v >> 5;          // 0..9
        const int col = v & 31;          // 0..31 (float4 index)
        const int gr = r0 - 1 + row;
        float4 val = make_float4(0.f, 0.f, 0.f, 0.f);
        if (gr >= 0 && gr < H)
            val = *reinterpret_cast<const float4*>(xp + (size_t)gr * W + c0 + col * 4);
        *reinterpret_cast<float4*>(&sm[row][4 + col * 4]) = val;
    }

    // ---- cooperative fill: left/right halo columns (20 scalars) ----
    if (tid < 2 * (TILE_H + 2)) {
        const int row  = tid >> 1;       // 0..9
        const int side = tid & 1;        // 0 = left, 1 = right
        const int gr = r0 - 1 + row;
        const int gc = side ? (c0 + TILE_W) : (c0 - 1);
        float val = 0.f;
        if (gr >= 0 && gr < H && gc >= 0 && gc < W)
            val = xp[(size_t)gr * W + gc];
        sm[row][side ? (4 + TILE_W) : 3] = val;
    }

    __syncthreads();

    // ---- compute: each thread -> 4 contiguous outputs ----
    const int i = threadIdx.y + 1;        // smem row of center
    const int j = 4 + threadIdx.x * 4;    // smem col of first output

    float t[6], m[6], b[6];
    #pragma unroll
    for (int k = 0; k < 6; k++) {
        t[k] = sm[i - 1][j - 1 + k];
        m[k] = sm[i    ][j - 1 + k];
        b[k] = sm[i + 1][j - 1 + k];
    }

    float4 o;
    float* op = &o.x;
    #pragma unroll
    for (int k = 0; k < 4; k++) {
        const float s = t[k] + t[k + 1] + t[k + 2]
                      + m[k]            + m[k + 2]
                      + b[k] + b[k + 1] + b[k + 2];
        op[k] = fabsf(0.125f * s - m[k + 1]) + 1e-5f;
    }

    *reinterpret_cast<float4*>(yp + (size_t)(r0 + threadIdx.y) * W + c0 + threadIdx.x * 4) = o;
}

extern "C" void kernel_launch(void* const* d_in, const int* in_sizes, int n_in,
                              void* d_out, int out_size) {
    const float* x = (const float*)d_in[0];
    float* y = (float*)d_out;

    const int planes = out_size / (W * H);  // 8*32 = 256
    dim3 block(32, 8, 1);
    dim3 grid(W / TILE_W, H / TILE_H, planes);  // (4, 64, 256)
    highpass_kernel<<<grid, block>>>(x, y);
}

// round 4
// speedup vs baseline: 1.3956x; 1.3956x over previous
#include <cuda_runtime.h>
#include <cuda_bf16.h>

// 3x3 high-pass stencil: y = |(1/8)*sum(8 neighbors) - center| + 1e-5
//                          = |0.125*(hs_top+hs_mid+hs_bot) - 1.125*center| + 1e-5
// where hs = horizontal 3-sum. x: (8,32,512,512) fp32, zero-padded SAME.
// Register-rolling, smem-free: each warp owns a 128-col x 16-row strip.

#define W 512
#define H 512
#define ROWS 16          // rows per warp strip
#define WARPS 8          // warps per CTA

__device__ __forceinline__ float4 load_row(const float* __restrict__ xp,
                                           int r, int col) {
    if (r < 0 || r >= H) return make_float4(0.f, 0.f, 0.f, 0.f);
    return *reinterpret_cast<const float4*>(xp + (size_t)r * W + col);
}

// horizontal 3-sums for the 4 elements this lane owns; lane-edge neighbors
// via warp shuffle, warp-strip edges via scalar global load (L1/L2 hit).
__device__ __forceinline__ float4 hsum_row(const float* __restrict__ xp,
                                           float4 v, int r, int c0, int lane) {
    const bool valid = (r >= 0 && r < H);
    float l = __shfl_up_sync(0xffffffffu, v.w, 1);
    if (lane == 0)
        l = (valid && c0 > 0) ? xp[(size_t)r * W + (c0 - 1)] : 0.f;
    float rr = __shfl_down_sync(0xffffffffu, v.x, 1);
    if (lane == 31)
        rr = (valid && c0 + 128 < W) ? xp[(size_t)r * W + (c0 + 128)] : 0.f;
    float4 h;
    h.x = l   + v.x + v.y;
    h.y = v.x + v.y + v.z;
    h.z = v.y + v.z + v.w;
    h.w = v.z + v.w + rr;
    return h;
}

__global__ __launch_bounds__(256)
void highpass_kernel(const float* __restrict__ x, float* __restrict__ y) {
    const int warp = threadIdx.x >> 5;
    const int lane = threadIdx.x & 31;
    const int plane = blockIdx.z;

    const int c0    = blockIdx.x * 128;                    // strip left col
    const int rbase = (blockIdx.y * WARPS + warp) * ROWS;  // strip top row
    const int col   = c0 + lane * 4;

    const float* __restrict__ xp = x + (size_t)plane * (W * H);
    float* __restrict__ yp       = y + (size_t)plane * (W * H);

    // prime the 3-row pipeline
    float4 v;
    v = load_row(xp, rbase - 1, col);
    float4 hs_prev = hsum_row(xp, v, rbase - 1, c0, lane);
    float4 v_cur = load_row(xp, rbase, col);
    float4 hs_cur = hsum_row(xp, v_cur, rbase, c0, lane);

    #pragma unroll 4
    for (int i = 0; i < ROWS; i++) {
        const int rn = rbase + i + 1;
        float4 v_next  = load_row(xp, rn, col);
        float4 hs_next = hsum_row(xp, v_next, rn, c0, lane);

        float4 o;
        o.x = fabsf(0.125f * (hs_prev.x + hs_cur.x + hs_next.x) - 1.125f * v_cur.x) + 1e-5f;
        o.y = fabsf(0.125f * (hs_prev.y + hs_cur.y + hs_next.y) - 1.125f * v_cur.y) + 1e-5f;
        o.z = fabsf(0.125f * (hs_prev.z + hs_cur.z + hs_next.z) - 1.125f * v_cur.z) + 1e-5f;
        o.w = fabsf(0.125f * (hs_prev.w + hs_cur.w + hs_next.w) - 1.125f * v_cur.w) + 1e-5f;

        *reinterpret_cast<float4*>(yp + (size_t)(rbase + i) * W + col) = o;

        hs_prev = hs_cur;
        hs_cur  = hs_next;
        v_cur   = v_next;
    }
}

extern "C" void kernel_launch(void* const* d_in, const int* in_sizes, int n_in,
                              void* d_out, int out_size) {
    const float* x = (const float*)d_in[0];
    float* y = (float*)d_out;

    const int planes = out_size / (W * H);        // 256
    dim3 block(256, 1, 1);                        // 8 warps
    dim3 grid(W / 128, H / (ROWS * WARPS), planes);  // (4, 4, 256) = 4096 CTAs
    highpass_kernel<<<grid, block>>>(x, y);
}

// round 7
// speedup vs baseline: 1.4508x; 1.0395x over previous
#include <cuda_runtime.h>
#include <cuda_bf16.h>

// 3x3 high-pass stencil: y = |(1/8)*sum(8 neighbors) - center| + 1e-5
//                          = |0.125*(hs_top+hs_mid+hs_bot) - 1.125*center| + 1e-5
// x: (8,32,512,512) fp32, zero-padded SAME. Register-rolling, smem-free.
// Each warp: 128-col x 32-row strip, prefetch distance 2 (vec + edge scalars).

#define W 512
#define H 512
#define ROWS 32          // rows per warp strip
#define WARPS 8          // warps per CTA
#define TW 128           // cols per warp strip

struct Row {
    float4 v;            // this lane's 4 columns
    float  l, r;         // strip-edge neighbors (lane 0 / lane 31 only)
};

// Issue all loads for one row (vec4 + predicated edge scalars). Consumed
// two iterations later, so DRAM/L2 latency is fully covered.
__device__ __forceinline__ Row load_row(const float* __restrict__ xp, int rr,
                                        int c0, int col, int lane) {
    Row o;
    o.l = 0.f; o.r = 0.f;
    if (rr >= 0 && rr < H) {
        o.v = *reinterpret_cast<const float4*>(xp + (size_t)rr * W + col);
        if (lane == 0  && c0 > 0)       o.l = xp[(size_t)rr * W + (c0 - 1)];
        if (lane == 31 && c0 + TW < W)  o.r = xp[(size_t)rr * W + (c0 + TW)];
    } else {
        o.v = make_float4(0.f, 0.f, 0.f, 0.f);
    }
    return o;
}

// Horizontal 3-sums from already-loaded row data; shuffles only.
__device__ __forceinline__ float4 hsum(const Row& rw, int lane) {
    float l = __shfl_up_sync(0xffffffffu, rw.v.w, 1);
    if (lane == 0) l = rw.l;
    float r = __shfl_down_sync(0xffffffffu, rw.v.x, 1);
    if (lane == 31) r = rw.r;
    float4 h;
    h.x = l      + rw.v.x + rw.v.y;
    h.y = rw.v.x + rw.v.y + rw.v.z;
    h.z = rw.v.y + rw.v.z + rw.v.w;
    h.w = rw.v.z + rw.v.w + r;
    return h;
}

__global__ __launch_bounds__(256, 4)
void highpass_kernel(const float* __restrict__ x, float* __restrict__ y) {
    const int warp  = threadIdx.x >> 5;
    const int lane  = threadIdx.x & 31;
    const int plane = blockIdx.z;

    const int c0    = blockIdx.x * TW;
    const int rbase = (blockIdx.y * WARPS + warp) * ROWS;
    const int col   = c0 + lane * 4;

    const float* __restrict__ xp = x + (size_t)plane * (W * H);
    float* __restrict__ yp       = y + (size_t)plane * (W * H);

    // prime: rows rbase-1 .. rbase+2 in flight / processed
    Row rm  = load_row(xp, rbase - 1, c0, col, lane);
    Row rc  = load_row(xp, rbase,     c0, col, lane);
    Row rn  = load_row(xp, rbase + 1, c0, col, lane);
    Row rn2 = load_row(xp, rbase + 2, c0, col, lane);

    float4 hsA = hsum(rm, lane);     // hs(r-1)
    float4 hsB = hsum(rc, lane);     // hs(r)
    float4 vc  = rc.v;               // center row values

    #pragma unroll 4
    for (int i = 0; i < ROWS; i++) {
        Row rn3 = load_row(xp, rbase + i + 3, c0, col, lane);  // prefetch d=2
        float4 hsC = hsum(rn, lane);                           // hs(r+1)

        float4 o;
        o.x = fabsf(0.125f * (hsA.x + hsB.x + hsC.x) - 1.125f * vc.x) + 1e-5f;
        o.y = fabsf(0.125f * (hsA.y + hsB.y + hsC.y) - 1.125f * vc.y) + 1e-5f;
        o.z = fabsf(0.125f * (hsA.z + hsB.z + hsC.z) - 1.125f * vc.z) + 1e-5f;
        o.w = fabsf(0.125f * (hsA.w + hsB.w + hsC.w) - 1.125f * vc.w) + 1e-5f;

        *reinterpret_cast<float4*>(yp + (size_t)(rbase + i) * W + col) = o;

        hsA = hsB; hsB = hsC; vc = rn.v; rn = rn2; rn2 = rn3;
    }
}

extern "C" void kernel_launch(void* const* d_in, const int* in_sizes, int n_in,
                              void* d_out, int out_size) {
    const float* x = (const float*)d_in[0];
    float* y = (float*)d_out;

    const int planes = out_size / (W * H);              // 256
    dim3 block(256, 1, 1);                              // 8 warps
    dim3 grid(W / TW, H / (ROWS * WARPS), planes);      // (4, 2, 256) = 2048 CTAs
    highpass_kernel<<<grid, block>>>(x, y);
}

// round 9
// speedup vs baseline: 1.4896x; 1.0267x over previous
#include <cuda_runtime.h>
#include <cuda_bf16.h>

// 3x3 high-pass stencil: y = |0.125*(hs_top+hs_mid+hs_bot) - 1.125*center| + 1e-5
// x: (8,32,512,512) fp32, zero-padded SAME. Register-rolling, smem-free.
// Warp strip: 128 cols x 32 rows, prefetch distance 2, streaming stores.

#define W 512
#define H 512
#define ROWS 32
#define WARPS 8
#define TW 128

struct Row {
    float4 v;     // lane's 4 columns
    float  l, r;  // strip-edge neighbors (lane 0 / 31)
};

__device__ __forceinline__ Row load_row(const float* __restrict__ xp, int rr,
                                        int c0, int col, int lane) {
    Row o;
    o.l = 0.f; o.r = 0.f;
    if (rr >= 0 && rr < H) {
        o.v = *reinterpret_cast<const float4*>(xp + rr * W + col);
        if (lane == 0  && c0 > 0)       o.l = xp[rr * W + (c0 - 1)];
        if (lane == 31 && c0 + TW < W)  o.r = xp[rr * W + (c0 + TW)];
    } else {
        o.v = make_float4(0.f, 0.f, 0.f, 0.f);
    }
    return o;
}

__device__ __forceinline__ float4 hsum(const Row& rw, int lane) {
    float l = __shfl_up_sync(0xffffffffu, rw.v.w, 1);
    if (lane == 0) l = rw.l;
    float r = __shfl_down_sync(0xffffffffu, rw.v.x, 1);
    if (lane == 31) r = rw.r;
    float4 h;
    h.x = l      + rw.v.x + rw.v.y;
    h.y = rw.v.x + rw.v.y + rw.v.z;
    h.z = rw.v.y + rw.v.z + rw.v.w;
    h.w = rw.v.z + rw.v.w + r;
    return h;
}

__global__ __launch_bounds__(256, 5)
void highpass_kernel(const float* __restrict__ x, float* __restrict__ y) {
    const int warp  = threadIdx.x >> 5;
    const int lane  = threadIdx.x & 31;

    const int c0    = blockIdx.x * TW;
    const int rbase = (blockIdx.y * WARPS + warp) * ROWS;
    const int col   = c0 + lane * 4;

    const float* __restrict__ xp = x + ((size_t)blockIdx.z << 18);
    float* __restrict__ yp       = y + ((size_t)blockIdx.z << 18);

    // prime the pipeline: rows rbase-1 .. rbase+2
    Row rm  = load_row(xp, rbase - 1, c0, col, lane);
    Row rc  = load_row(xp, rbase,     c0, col, lane);
    Row rn  = load_row(xp, rbase + 1, c0, col, lane);
    Row rn2 = load_row(xp, rbase + 2, c0, col, lane);

    float4 hsA = hsum(rm, lane);
    float4 hsB = hsum(rc, lane);
    float4 vc  = rc.v;

    float* op = yp + rbase * W + col;

    #pragma unroll 4
    for (int i = 0; i < ROWS; i++) {
        Row rn3 = load_row(xp, rbase + i + 3, c0, col, lane);  // prefetch d=2
        float4 hsC = hsum(rn, lane);

        float4 o;
        o.x = fabsf(0.125f * (hsA.x + hsB.x + hsC.x) - 1.125f * vc.x) + 1e-5f;
        o.y = fabsf(0.125f * (hsA.y + hsB.y + hsC.y) - 1.125f * vc.y) + 1e-5f;
        o.z = fabsf(0.125f * (hsA.z + hsB.z + hsC.z) - 1.125f * vc.z) + 1e-5f;
        o.w = fabsf(0.125f * (hsA.w + hsB.w + hsC.w) - 1.125f * vc.w) + 1e-5f;

        __stcs(reinterpret_cast<float4*>(op), o);   // streaming store: no reuse
        op += W;

        hsA = hsB; hsB = hsC; vc = rn.v; rn = rn2; rn2 = rn3;
    }
}

extern "C" void kernel_launch(void* const* d_in, const int* in_sizes, int n_in,
                              void* d_out, int out_size) {
    const float* x = (const float*)d_in[0];
    float* y = (float*)d_out;

    const int planes = out_size / (W * H);           // 256
    dim3 block(256, 1, 1);
    dim3 grid(W / TW, H / (ROWS * WARPS), planes);   // (4, 2, 256) = 2048 CTAs
    highpass_kernel<<<grid, block>>>(x, y);
}